// round 8
// baseline (speedup 1.0000x reference)
#include <cuda_runtime.h>
#include <cuda_bf16.h>

// Problem constants (fixed by the reference setup)
#define N_BATCH 8
#define C_CH    490     // OUTPUT_DIM * GROUP * GROUP = 10*49
#define H_DIM   64
#define W_DIM   64
#define R_ROIS  2000
#define D_OUT   10
#define G_GRP   7
#define IH      65      // H+1
#define IW      65      // W+1
#define SPATIAL_SCALE 0.0625f

// 66.25 MB fp32 scratch for the padded integral image, layout (N, C, 65, 65).
__device__ float g_integ[N_BATCH * C_CH * IH * IW];

// ---------------------------------------------------------------------------
// Kernel 1: per-plane padded integral image, replicating
//   integ = pad(cumsum(cumsum(feature, axis=H), axis=W))
// in fp32, sequential accumulation, H first then W, rn adds.
// One block of 128 threads per (n, c) plane.
// ---------------------------------------------------------------------------
__global__ void __launch_bounds__(128) integral_kernel(const float* __restrict__ feature) {
    __shared__ float tile[H_DIM * (W_DIM + 1)];   // 64 x 65 floats (stride 65)

    const int plane = blockIdx.x;                 // 0 .. N*C-1
    const int tid = threadIdx.x;
    const float* __restrict__ src = feature + (size_t)plane * (H_DIM * W_DIM);

    // Coalesced tile load
    #pragma unroll
    for (int i = tid; i < H_DIM * W_DIM; i += 128) {
        int row = i >> 6;
        int col = i & 63;
        tile[row * (W_DIM + 1) + col] = src[i];
    }
    __syncthreads();

    // Pass 1: cumsum along H (axis=2). Thread t owns column t. Conflict-free.
    if (tid < W_DIM) {
        float s = 0.f;
        #pragma unroll
        for (int r = 0; r < H_DIM; ++r) {
            s = __fadd_rn(s, tile[r * (W_DIM + 1) + tid]);
            tile[r * (W_DIM + 1) + tid] = s;
        }
    }
    __syncthreads();

    // Pass 2: cumsum along W (axis=3). Thread t owns row t. Stride 65: conflict-free.
    if (tid < H_DIM) {
        float s = 0.f;
        float* rp = tile + tid * (W_DIM + 1);
        #pragma unroll
        for (int c = 0; c < W_DIM; ++c) {
            s = __fadd_rn(s, rp[c]);
            rp[c] = s;
        }
    }
    __syncthreads();

    // Coalesced store of padded 65x65 integral (row 0 / col 0 are zeros).
    float* __restrict__ dst = g_integ + (size_t)plane * (IH * IW);
    for (int i = tid; i < IH * IW; i += 128) {
        const int row = i / IW;
        const int col = i - row * IW;
        float v = 0.f;
        if (row > 0 && col > 0)
            v = tile[(row - 1) * (W_DIM + 1) + (col - 1)];
        dst[i] = v;
    }
}

// ---------------------------------------------------------------------------
// Kernel 2: PSRoI pooling from the fp32 integral image.
// One thread per output element; output store address == tid (coalesced).
//
// Boundary math hypothesis (from R1..R6 evidence):
//   - bh = roi_h * fl(1/7)   (XLA rewrites divide-by-constant to reciprocal
//     multiply; the divide-based bh of R2..R6 flips ~hundreds of floor/ceil
//     results at the (7m+gk)/112 exact-integer points -> the fixed 1.71e-2)
//   - boundaries as SEPARATE rn mul + rn add (no FMA): R1 (which contracted
//     to FMA) retained a 4e-3 residual.
// ---------------------------------------------------------------------------
__global__ void __launch_bounds__(256) psroipool_kernel(const float* __restrict__ rois,
                                                        float* __restrict__ out,
                                                        int total) {
    const int tid = blockIdx.x * blockDim.x + threadIdx.x;
    if (tid >= total) return;

    const int r   = tid / C_CH;
    const int c   = tid - r * C_CH;        // = d*49 + gh*7 + gw  (channel)
    const int g2  = c % (G_GRP * G_GRP);   // gh*7 + gw
    const int gh  = g2 / G_GRP;
    const int gw  = g2 - gh * G_GRP;

    const float* roi = rois + r * 5;
    const int b = (int)roi[0];

    // round half-to-even (rintf), then *1/16 (exact power of two)
    const float rsw = __fmul_rn(rintf(roi[1]), SPATIAL_SCALE);
    const float rsh = __fmul_rn(rintf(roi[2]), SPATIAL_SCALE);
    const float rew = __fmul_rn(rintf(__fadd_rn(roi[3], 1.0f)), SPATIAL_SCALE);
    const float reh = __fmul_rn(rintf(__fadd_rn(roi[4], 1.0f)), SPATIAL_SCALE);

    const float roi_w = fmaxf(__fsub_rn(rew, rsw), 0.1f);
    const float roi_h = fmaxf(__fsub_rn(reh, rsh), 0.1f);

    // Reciprocal multiply: fl(1/7) computed at compile time (round-to-nearest)
    const float INV7 = 1.0f / 7.0f;
    const float bw = __fmul_rn(roi_w, INV7);
    const float bh = __fmul_rn(roi_h, INV7);

    // Separate rn mul then rn add — NO FMA contraction possible
    const float ghf  = (float)gh,  gwf  = (float)gw;
    const float gh1f = ghf + 1.0f, gw1f = gwf + 1.0f;   // exact small ints

    float hs_f = floorf(__fadd_rn(rsh, __fmul_rn(ghf,  bh)));
    float he_f = ceilf (__fadd_rn(rsh, __fmul_rn(gh1f, bh)));
    float ws_f = floorf(__fadd_rn(rsw, __fmul_rn(gwf,  bw)));
    float we_f = ceilf (__fadd_rn(rsw, __fmul_rn(gw1f, bw)));

    hs_f = fminf(fmaxf(hs_f, 0.f), (float)H_DIM);
    he_f = fminf(fmaxf(he_f, 0.f), (float)H_DIM);
    ws_f = fminf(fmaxf(ws_f, 0.f), (float)W_DIM);
    we_f = fminf(fmaxf(we_f, 0.f), (float)W_DIM);
    const int hs = (int)hs_f, he = (int)he_f, ws = (int)ws_f, we = (int)we_f;

    const float* __restrict__ I = g_integ + ((size_t)(b * C_CH + c)) * (IH * IW);

    const float a00 = I[he * IW + we];   // pick(he, we)
    const float a01 = I[hs * IW + we];   // pick(hs, we)
    const float a10 = I[he * IW + ws];   // pick(he, ws)
    const float a11 = I[hs * IW + ws];   // pick(hs, ws)

    // reference order: ((a - b) - c) + d, each step rn fp32
    const float s = __fadd_rn(__fsub_rn(__fsub_rn(a00, a01), a10), a11);

    const int area = (he - hs) * (we - ws);
    const float area_f = fmaxf((float)area, 1.0f);
    out[tid] = (area <= 0) ? 0.f : __fdiv_rn(s, area_f);
}

extern "C" void kernel_launch(void* const* d_in, const int* in_sizes, int n_in,
                              void* d_out, int out_size) {
    const float* feature = (const float*)d_in[0];   // (8, 490, 64, 64) fp32
    const float* rois    = (const float*)d_in[1];   // (2000, 5) fp32
    float* out = (float*)d_out;                     // (2000, 10, 7, 7) fp32

    const int total = R_ROIS * D_OUT * G_GRP * G_GRP;   // 980000

    integral_kernel<<<N_BATCH * C_CH, 128>>>(feature);
    psroipool_kernel<<<(total + 255) / 256, 256>>>(rois, out, total);
}

// round 9
// speedup vs baseline: 1.4273x; 1.4273x over previous
#include <cuda_runtime.h>
#include <cuda_bf16.h>
#include <stdint.h>

// Problem constants (fixed by the reference setup)
#define N_BATCH 8
#define C_CH    490     // OUTPUT_DIM * GROUP * GROUP = 10*49
#define H_DIM   64
#define W_DIM   64
#define R_ROIS  2000
#define G_GRP   7
#define G2_CNT  49      // 7*7
#define SPATIAL_SCALE 0.0625f

#define P_STRIDE 67     // padded smem row stride (gcd(67,32)=1: conflict-free column walks)

// Small scratch: packed bin bounds per (roi, g2), ROI list bucketed by batch.
__device__ uint32_t g_bounds[R_ROIS * G2_CNT];   // 392 KB (L2-resident)
__device__ int      g_roi_sorted[R_ROIS];
__device__ int      g_batch_start[N_BATCH + 1];

// ---------------------------------------------------------------------------
// Prep A: bucket ROI indices by batch. One block.
// ---------------------------------------------------------------------------
__global__ void __launch_bounds__(256) bucket_kernel(const float* __restrict__ rois) {
    __shared__ int counts[N_BATCH];
    __shared__ int cursor[N_BATCH];
    const int tid = threadIdx.x;

    if (tid < N_BATCH) counts[tid] = 0;
    __syncthreads();

    for (int i = tid; i < R_ROIS; i += 256) {
        int b = (int)rois[i * 5];
        atomicAdd(&counts[b], 1);
    }
    __syncthreads();

    if (tid == 0) {
        int acc = 0;
        for (int n = 0; n < N_BATCH; ++n) {
            g_batch_start[n] = acc;
            cursor[n] = acc;
            acc += counts[n];
        }
        g_batch_start[N_BATCH] = acc;
    }
    __syncthreads();

    for (int i = tid; i < R_ROIS; i += 256) {
        int b = (int)rois[i * 5];
        int pos = atomicAdd(&cursor[b], 1);
        g_roi_sorted[pos] = i;
    }
}

// ---------------------------------------------------------------------------
// Prep B: per-(roi, g2) bin bounds, packed 4x8 bits.
// EXACT arithmetic chain validated in R8 (rel_err 1.7e-6):
//   bh = roi_h * fl(1/7) (reciprocal multiply), boundaries as SEPARATE
//   __fmul_rn + __fadd_rn (no FMA contraction).
// ---------------------------------------------------------------------------
__global__ void __launch_bounds__(256) bounds_kernel(const float* __restrict__ rois) {
    const int tid = blockIdx.x * blockDim.x + threadIdx.x;
    if (tid >= R_ROIS * G2_CNT) return;

    const int r  = tid / G2_CNT;
    const int g2 = tid - r * G2_CNT;
    const int gh = g2 / G_GRP;
    const int gw = g2 - gh * G_GRP;

    const float* roi = rois + r * 5;

    const float rsw = __fmul_rn(rintf(roi[1]), SPATIAL_SCALE);
    const float rsh = __fmul_rn(rintf(roi[2]), SPATIAL_SCALE);
    const float rew = __fmul_rn(rintf(__fadd_rn(roi[3], 1.0f)), SPATIAL_SCALE);
    const float reh = __fmul_rn(rintf(__fadd_rn(roi[4], 1.0f)), SPATIAL_SCALE);

    const float roi_w = fmaxf(__fsub_rn(rew, rsw), 0.1f);
    const float roi_h = fmaxf(__fsub_rn(reh, rsh), 0.1f);

    const float INV7 = 1.0f / 7.0f;                  // fl(1/7), compile-time rn
    const float bw = __fmul_rn(roi_w, INV7);
    const float bh = __fmul_rn(roi_h, INV7);

    const float ghf  = (float)gh,  gwf  = (float)gw;
    const float gh1f = ghf + 1.0f, gw1f = gwf + 1.0f;

    float hs_f = floorf(__fadd_rn(rsh, __fmul_rn(ghf,  bh)));
    float he_f = ceilf (__fadd_rn(rsh, __fmul_rn(gh1f, bh)));
    float ws_f = floorf(__fadd_rn(rsw, __fmul_rn(gwf,  bw)));
    float we_f = ceilf (__fadd_rn(rsw, __fmul_rn(gw1f, bw)));

    hs_f = fminf(fmaxf(hs_f, 0.f), (float)H_DIM);
    he_f = fminf(fmaxf(he_f, 0.f), (float)H_DIM);
    ws_f = fminf(fmaxf(ws_f, 0.f), (float)W_DIM);
    we_f = fminf(fmaxf(we_f, 0.f), (float)W_DIM);

    const uint32_t hs = (uint32_t)(int)hs_f;
    const uint32_t he = (uint32_t)(int)he_f;
    const uint32_t ws = (uint32_t)(int)ws_f;
    const uint32_t we = (uint32_t)(int)we_f;

    g_bounds[tid] = hs | (he << 8) | (ws << 16) | (we << 24);
}

// ---------------------------------------------------------------------------
// Fused kernel: one block per (n, c) plane.
//  1) build the padded 65x65 fp32 integral image in smem (reference op order:
//     sequential rn cumsum along H, then along W)
//  2) pool directly from smem for every ROI of batch n (this plane contributes
//     exactly one output element per ROI: out[r*490 + c])
// The 66 MB integral never touches DRAM.
// ---------------------------------------------------------------------------
__global__ void __launch_bounds__(128) fused_kernel(const float* __restrict__ feature,
                                                    float* __restrict__ out) {
    __shared__ float P[(H_DIM + 1) * P_STRIDE];   // padded integral, 17.4 KB

    const int plane = blockIdx.x;                 // 0 .. N*C-1
    const int n  = plane / C_CH;
    const int c  = plane - n * C_CH;              // = d*49 + g2
    const int g2 = c % G2_CNT;
    const int tid = threadIdx.x;

    const float* __restrict__ src = feature + (size_t)plane * (H_DIM * W_DIM);

    // Zero padding row 0 and column 0
    for (int i = tid; i < (H_DIM + 1); i += 128) {
        P[i] = 0.f;                               // row 0, cols 0..64 (partial; rest below)
        P[i * P_STRIDE] = 0.f;                    // col 0, rows 0..64
    }
    if (tid == 0) P[64] = 0.f;                    // ensure full row 0 covered (cols 0..64)
    __syncthreads();

    // Coalesced interior load: P[(row+1)*stride + col+1] = src[row*64+col]
    #pragma unroll
    for (int i = tid; i < H_DIM * W_DIM; i += 128) {
        int row = i >> 6;
        int col = i & 63;
        P[(row + 1) * P_STRIDE + (col + 1)] = src[i];
    }
    __syncthreads();

    // Pass 1: cumsum along H (axis=2). Thread t owns column t+1. Conflict-free.
    if (tid < W_DIM) {
        float s = 0.f;
        #pragma unroll
        for (int r = 1; r <= H_DIM; ++r) {
            s = __fadd_rn(s, P[r * P_STRIDE + (tid + 1)]);
            P[r * P_STRIDE + (tid + 1)] = s;
        }
    }
    __syncthreads();

    // Pass 2: cumsum along W (axis=3). Thread t owns row t+1. Stride 67: conflict-free.
    if (tid < H_DIM) {
        float s = 0.f;
        float* rp = P + (tid + 1) * P_STRIDE;
        #pragma unroll
        for (int cc = 1; cc <= W_DIM; ++cc) {
            s = __fadd_rn(s, rp[cc]);
            rp[cc] = s;
        }
    }
    __syncthreads();

    // Pooling: this plane serves one output per ROI of batch n.
    const int s_idx = g_batch_start[n];
    const int e_idx = g_batch_start[n + 1];

    for (int i = s_idx + tid; i < e_idx; i += 128) {
        const int r = g_roi_sorted[i];
        const uint32_t pk = g_bounds[r * G2_CNT + g2];
        const int hs = (int)(pk & 0xFF);
        const int he = (int)((pk >> 8) & 0xFF);
        const int ws = (int)((pk >> 16) & 0xFF);
        const int we = (int)(pk >> 24);

        const float a00 = P[he * P_STRIDE + we];
        const float a01 = P[hs * P_STRIDE + we];
        const float a10 = P[he * P_STRIDE + ws];
        const float a11 = P[hs * P_STRIDE + ws];

        // reference order: ((a - b) - c) + d, each step rn fp32
        const float sum = __fadd_rn(__fsub_rn(__fsub_rn(a00, a01), a10), a11);

        const int area = (he - hs) * (we - ws);
        const float area_f = fmaxf((float)area, 1.0f);
        out[(size_t)r * C_CH + c] = (area <= 0) ? 0.f : __fdiv_rn(sum, area_f);
    }
}

extern "C" void kernel_launch(void* const* d_in, const int* in_sizes, int n_in,
                              void* d_out, int out_size) {
    const float* feature = (const float*)d_in[0];   // (8, 490, 64, 64) fp32
    const float* rois    = (const float*)d_in[1];   // (2000, 5) fp32
    float* out = (float*)d_out;                     // (2000, 10, 7, 7) fp32

    bucket_kernel<<<1, 256>>>(rois);
    bounds_kernel<<<(R_ROIS * G2_CNT + 255) / 256, 256>>>(rois);
    fused_kernel<<<N_BATCH * C_CH, 128>>>(feature, out);
}

// round 10
// speedup vs baseline: 1.6169x; 1.1328x over previous
#include <cuda_runtime.h>
#include <cuda_bf16.h>
#include <stdint.h>

// Problem constants (fixed by the reference setup)
#define N_BATCH 8
#define C_CH    490     // OUTPUT_DIM * GROUP * GROUP = 10*49
#define H_DIM   64
#define W_DIM   64
#define R_ROIS  2000
#define D_OUT   10
#define G_GRP   7
#define G2_CNT  49      // 7*7
#define SPATIAL_SCALE 0.0625f

#define IHP     65      // H+1 rows in padded integral
#define P_STRIDE 67     // padded smem row stride (gcd(67,32)=1: conflict-free)
#define PLANE_F (IHP * P_STRIDE)   // 4355 floats per plane

// Small scratch (L2-resident): packed bin bounds per (roi, g2), batch buckets.
__device__ uint32_t g_bounds[R_ROIS * G2_CNT];   // 392 KB
__device__ int      g_roi_sorted[R_ROIS];
__device__ int      g_batch_start[N_BATCH + 1];

// ---------------------------------------------------------------------------
// Prep (single launch): block 0 buckets ROIs by batch; all other blocks
// compute packed bin bounds. The two run concurrently, hiding the bucket
// block's serial latency (was a standalone 8us kernel in R9).
// Bounds math: EXACT chain validated in R8/R9 (rel_err 1.7e-6):
//   bh = roi_h * fl(1/7)  (reciprocal multiply, XLA-style)
//   boundaries = SEPARATE __fmul_rn + __fadd_rn (no FMA contraction)
// ---------------------------------------------------------------------------
__global__ void __launch_bounds__(256) prep_kernel(const float* __restrict__ rois) {
    const int tid = threadIdx.x;

    if (blockIdx.x == 0) {
        // ---- bucketing ----
        __shared__ int counts[N_BATCH];
        __shared__ int cursor[N_BATCH];
        if (tid < N_BATCH) counts[tid] = 0;
        __syncthreads();
        for (int i = tid; i < R_ROIS; i += 256) {
            int b = (int)rois[i * 5];
            atomicAdd(&counts[b], 1);
        }
        __syncthreads();
        if (tid == 0) {
            int acc = 0;
            for (int n = 0; n < N_BATCH; ++n) {
                g_batch_start[n] = acc;
                cursor[n] = acc;
                acc += counts[n];
            }
            g_batch_start[N_BATCH] = acc;
        }
        __syncthreads();
        for (int i = tid; i < R_ROIS; i += 256) {
            int b = (int)rois[i * 5];
            int pos = atomicAdd(&cursor[b], 1);
            g_roi_sorted[pos] = i;
        }
        return;
    }

    // ---- bounds ----
    const int idx = (blockIdx.x - 1) * 256 + tid;
    if (idx >= R_ROIS * G2_CNT) return;

    const int r  = idx / G2_CNT;
    const int g2 = idx - r * G2_CNT;
    const int gh = g2 / G_GRP;
    const int gw = g2 - gh * G_GRP;

    const float* roi = rois + r * 5;

    const float rsw = __fmul_rn(rintf(roi[1]), SPATIAL_SCALE);
    const float rsh = __fmul_rn(rintf(roi[2]), SPATIAL_SCALE);
    const float rew = __fmul_rn(rintf(__fadd_rn(roi[3], 1.0f)), SPATIAL_SCALE);
    const float reh = __fmul_rn(rintf(__fadd_rn(roi[4], 1.0f)), SPATIAL_SCALE);

    const float roi_w = fmaxf(__fsub_rn(rew, rsw), 0.1f);
    const float roi_h = fmaxf(__fsub_rn(reh, rsh), 0.1f);

    const float INV7 = 1.0f / 7.0f;                  // fl(1/7), compile-time rn
    const float bw = __fmul_rn(roi_w, INV7);
    const float bh = __fmul_rn(roi_h, INV7);

    const float ghf  = (float)gh,  gwf  = (float)gw;
    const float gh1f = ghf + 1.0f, gw1f = gwf + 1.0f;

    float hs_f = floorf(__fadd_rn(rsh, __fmul_rn(ghf,  bh)));
    float he_f = ceilf (__fadd_rn(rsh, __fmul_rn(gh1f, bh)));
    float ws_f = floorf(__fadd_rn(rsw, __fmul_rn(gwf,  bw)));
    float we_f = ceilf (__fadd_rn(rsw, __fmul_rn(gw1f, bw)));

    hs_f = fminf(fmaxf(hs_f, 0.f), (float)H_DIM);
    he_f = fminf(fmaxf(he_f, 0.f), (float)H_DIM);
    ws_f = fminf(fmaxf(ws_f, 0.f), (float)W_DIM);
    we_f = fminf(fmaxf(we_f, 0.f), (float)W_DIM);

    g_bounds[idx] = (uint32_t)(int)hs_f
                  | ((uint32_t)(int)he_f << 8)
                  | ((uint32_t)(int)ws_f << 16)
                  | ((uint32_t)(int)we_f << 24);
}

// ---------------------------------------------------------------------------
// Fused kernel: TWO planes per block, same g2 (so they share bin bounds),
// d-pair (2k, 2k+1). Threads 0..63 build plane A's integral in smem, threads
// 64..127 build plane B's — all 128 threads active in both scan passes.
// Then all threads pool: one packed-bounds load serves both planes.
// Scan is the reference's exact fp32 op order (H cumsum then W cumsum, rn).
// ---------------------------------------------------------------------------
__global__ void __launch_bounds__(128) fused_kernel(const float* __restrict__ feature,
                                                    float* __restrict__ out) {
    __shared__ float P[2 * PLANE_F];              // 34.8 KB

    const int bid = blockIdx.x;                   // 0 .. 8*245-1
    const int n   = bid / (G2_CNT * (D_OUT / 2)); // / 245
    const int rem = bid - n * (G2_CNT * (D_OUT / 2));
    const int g2  = rem / (D_OUT / 2);
    const int k   = rem - g2 * (D_OUT / 2);       // 0..4
    const int c1  = (2 * k)     * G2_CNT + g2;
    const int c2  = (2 * k + 1) * G2_CNT + g2;

    const int tid  = threadIdx.x;
    const int half = tid >> 6;                    // 0: plane A, 1: plane B
    const int t    = tid & 63;

    float* __restrict__ Pb = P + half * PLANE_F;
    const int my_c = half ? c2 : c1;
    const float* __restrict__ src =
        feature + ((size_t)(n * C_CH + my_c)) * (H_DIM * W_DIM);

    // Zero padding: row 0 (cols 0..64) and column 0 (rows 0..64) of my plane
    for (int i = t; i < IHP; i += 64) {
        Pb[i] = 0.f;                              // row 0
        Pb[i * P_STRIDE] = 0.f;                   // col 0
    }

    // Vectorized interior load: 1024 float4 per plane, 16 per thread
    {
        const float4* __restrict__ src4 = (const float4*)src;
        #pragma unroll
        for (int i = t; i < (H_DIM * W_DIM) / 4; i += 64) {
            const float4 v = src4[i];
            const int row  = i >> 4;              // i*4 / 64
            const int col0 = (i & 15) << 2;       // (i*4) % 64
            float* p = Pb + (row + 1) * P_STRIDE + (col0 + 1);
            p[0] = v.x; p[1] = v.y; p[2] = v.z; p[3] = v.w;
        }
    }
    __syncthreads();

    // Pass 1: cumsum along H (axis=2). Thread t owns column t+1 of its plane.
    {
        float s = 0.f;
        #pragma unroll
        for (int r = 1; r <= H_DIM; ++r) {
            s = __fadd_rn(s, Pb[r * P_STRIDE + (t + 1)]);
            Pb[r * P_STRIDE + (t + 1)] = s;
        }
    }
    __syncthreads();

    // Pass 2: cumsum along W (axis=3). Thread t owns row t+1 of its plane.
    {
        float s = 0.f;
        float* rp = Pb + (t + 1) * P_STRIDE;
        #pragma unroll
        for (int cc = 1; cc <= W_DIM; ++cc) {
            s = __fadd_rn(s, rp[cc]);
            rp[cc] = s;
        }
    }
    __syncthreads();

    // Pooling: every thread serves both planes (shared bounds per ROI).
    const float* __restrict__ A = P;              // plane c1
    const float* __restrict__ B = P + PLANE_F;    // plane c2
    const int s_idx = g_batch_start[n];
    const int e_idx = g_batch_start[n + 1];

    for (int i = s_idx + tid; i < e_idx; i += 128) {
        const int r = g_roi_sorted[i];
        const uint32_t pk = g_bounds[r * G2_CNT + g2];
        const int hs = (int)(pk & 0xFF);
        const int he = (int)((pk >> 8) & 0xFF);
        const int ws = (int)((pk >> 16) & 0xFF);
        const int we = (int)(pk >> 24);

        const int o00 = he * P_STRIDE + we;
        const int o01 = hs * P_STRIDE + we;
        const int o10 = he * P_STRIDE + ws;
        const int o11 = hs * P_STRIDE + ws;

        // reference order: ((a - b) - c) + d, each step rn fp32
        const float sA = __fadd_rn(__fsub_rn(__fsub_rn(A[o00], A[o01]), A[o10]), A[o11]);
        const float sB = __fadd_rn(__fsub_rn(__fsub_rn(B[o00], B[o01]), B[o10]), B[o11]);

        const int area = (he - hs) * (we - ws);
        const float area_f = fmaxf((float)area, 1.0f);
        const bool empty = (area <= 0);

        float* op = out + (size_t)r * C_CH;
        op[c1] = empty ? 0.f : __fdiv_rn(sA, area_f);
        op[c2] = empty ? 0.f : __fdiv_rn(sB, area_f);
    }
}

extern "C" void kernel_launch(void* const* d_in, const int* in_sizes, int n_in,
                              void* d_out, int out_size) {
    const float* feature = (const float*)d_in[0];   // (8, 490, 64, 64) fp32
    const float* rois    = (const float*)d_in[1];   // (2000, 5) fp32
    float* out = (float*)d_out;                     // (2000, 10, 7, 7) fp32

    const int bounds_blocks = (R_ROIS * G2_CNT + 255) / 256;   // 383
    prep_kernel<<<1 + bounds_blocks, 256>>>(rois);
    fused_kernel<<<N_BATCH * G2_CNT * (D_OUT / 2), 128>>>(feature, out);
}